// round 16
// baseline (speedup 1.0000x reference)
#include <cuda_runtime.h>
#include <cuda_fp16.h>
#include <math.h>
#include <stdint.h>

// Problem constants
#define BB 2
#define TT 2048
#define CC 1024
#define HH 16
#define DD 64
#define M_TOK (BB*TT)     // 4096
#define N_QKV (3*CC)      // 3072

// Scratch (allocation-free rule: __device__ globals)
__device__ __half g_qkv[M_TOK * N_QKV];  // 24 MB
__device__ __half g_y[M_TOK * CC];       //  8 MB
__device__ __half g_xh[M_TOK * CC];      //  8 MB
__device__ __half g_wa[N_QKV * CC];      //  6 MB : W_attn^T [N,K]
__device__ __half g_wp[CC * CC];         //  2 MB : W_proj^T [N,K]

// ---------------------------------------------------------------------------
// helpers
// ---------------------------------------------------------------------------
__device__ __forceinline__ unsigned pack_h2(float a, float b) {
    __half2 h = __floats2half2_rn(a, b);
    return *reinterpret_cast<unsigned*>(&h);
}

__device__ __forceinline__ void mma_h(float c[4], const unsigned a[4], const unsigned b[2]) {
    asm volatile(
        "mma.sync.aligned.m16n8k16.row.col.f32.f16.f16.f32 "
        "{%0,%1,%2,%3}, {%4,%5,%6,%7}, {%8,%9}, {%0,%1,%2,%3};\n"
        : "+f"(c[0]), "+f"(c[1]), "+f"(c[2]), "+f"(c[3])
        : "r"(a[0]), "r"(a[1]), "r"(a[2]), "r"(a[3]), "r"(b[0]), "r"(b[1]));
}

__device__ __forceinline__ void ldm_x4(unsigned& r0, unsigned& r1, unsigned& r2, unsigned& r3,
                                       uint32_t addr) {
    asm volatile("ldmatrix.sync.aligned.m8n8.x4.shared.b16 {%0,%1,%2,%3}, [%4];"
                 : "=r"(r0), "=r"(r1), "=r"(r2), "=r"(r3) : "r"(addr));
}
__device__ __forceinline__ void ldm_x4_t(unsigned& r0, unsigned& r1, unsigned& r2, unsigned& r3,
                                         uint32_t addr) {
    asm volatile("ldmatrix.sync.aligned.m8n8.x4.trans.shared.b16 {%0,%1,%2,%3}, [%4];"
                 : "=r"(r0), "=r"(r1), "=r"(r2), "=r"(r3) : "r"(addr));
}

__device__ __forceinline__ void cp_async16(void* smem, const void* gmem) {
    unsigned saddr = (unsigned)__cvta_generic_to_shared(smem);
    asm volatile("cp.async.cg.shared.global [%0], [%1], 16;\n" :: "r"(saddr), "l"(gmem));
}
#define CP_COMMIT() asm volatile("cp.async.commit_group;\n" ::: "memory")
#define CP_WAIT1()  asm volatile("cp.async.wait_group 1;\n" ::: "memory")

// ---------------------------------------------------------------------------
// pre-pass kernels
// ---------------------------------------------------------------------------
__global__ void to_half_kernel(const float* __restrict__ in, unsigned* __restrict__ out, int n4)
{
    int i = blockIdx.x * blockDim.x + threadIdx.x;
    if (i < n4) {
        float4 v = ((const float4*)in)[i];
        uint2 o;
        o.x = pack_h2(v.x, v.y);
        o.y = pack_h2(v.z, v.w);
        ((uint2*)out)[i] = o;
    }
}

__global__ void transpose_h_kernel(const float* __restrict__ in, __half* __restrict__ out,
                                   int K, int N)
{
    __shared__ float tile[32][33];
    int k0 = blockIdx.y * 32, n0 = blockIdx.x * 32;
    int tx = threadIdx.x, ty = threadIdx.y;
    #pragma unroll
    for (int j = 0; j < 4; ++j)
        tile[ty + 8*j][tx] = in[(size_t)(k0 + ty + 8*j) * N + n0 + tx];
    __syncthreads();
    #pragma unroll
    for (int j = 0; j < 4; ++j)
        out[(size_t)(n0 + ty + 8*j) * K + k0 + tx] = __float2half_rn(tile[tx][ty + 8*j]);
}

// ---------------------------------------------------------------------------
// fp16 GEMM v3: BM=128, BN=128, BK=64, 256 threads, 2 CTAs/SM, ldmatrix frags.
// Warp tile 64x32 (8 warps, 2 along M x 4 along N). 3-stage cp.async.
// C[M,N] = A[M,K] @ Bt[N,K]^T + bias[N].
// ---------------------------------------------------------------------------
#define GBM 128
#define GBN 128
#define GBK 64
#define HNST 3
#define HPI 72                      // pitch (halves); 144B rows, validated conflict-free
#define HAST (GBM * HPI)            // 9216 halves / stage
#define HBST (GBN * HPI)
#define GEMMH_SMEM ((HNST*(HAST + HBST)) * 2)   // 110592 B

template<int OUTF32>
__global__ __launch_bounds__(256, 2)
void gemm_h(const __half* __restrict__ A, const __half* __restrict__ Bt,
            const float* __restrict__ bias, void* __restrict__ Cout,
            int Mdim, int Ndim, int Kdim)
{
    extern __shared__ __half hsm[];
    __half* As = hsm;                       // [HNST][128][HPI]
    __half* Bs = hsm + HNST * HAST;         // [HNST][128][HPI]

    const int tid  = threadIdx.x;
    const int lane = tid & 31;
    const int wid  = tid >> 5;
    const int g    = lane >> 2;
    const int t    = lane & 3;
    const int warp_m = wid & 1;             // 2 warps along M (64 rows)
    const int warp_n = wid >> 1;            // 4 warps along N (32 cols)
    const int m0 = blockIdx.y * GBM;
    const int n0 = blockIdx.x * GBN;

    // cp.async mapping: row = tid>>1, half-row = tid&1 (32 halves), 4 x 16B ops each
    const int arow = tid >> 1, ah = tid & 1;

    const __half* Ap = A  + (size_t)(m0 + arow) * Kdim + ah * 32;
    const __half* Bp = Bt + (size_t)(n0 + arow) * Kdim + ah * 32;

    __half* Asw = As + arow * HPI + ah * 32;
    __half* Bsw = Bs + arow * HPI + ah * 32;

    // ldmatrix per-lane offsets (byte)
    const int grp = lane >> 3, l7 = lane & 7;
    const uint32_t asm32 = (uint32_t)__cvta_generic_to_shared(As);
    const uint32_t bsm32 = (uint32_t)__cvta_generic_to_shared(Bs);
    const uint32_t aoff = ((uint32_t)(warp_m*64 + (lane & 15)) * HPI + (uint32_t)(lane >> 4) * 8) * 2;
    const uint32_t boff = ((uint32_t)(warp_n*32 + (grp >> 1)*8 + l7) * HPI) * 2 + (uint32_t)(grp & 1) * 16;

    float c[4][4][4];
    #pragma unroll
    for (int mi = 0; mi < 4; ++mi)
        #pragma unroll
        for (int ni = 0; ni < 4; ++ni)
            #pragma unroll
            for (int j = 0; j < 4; ++j) c[mi][ni][j] = 0.f;

    const int ntiles = Kdim / GBK;          // 16

    // prologue: fill stages 0,1
    #pragma unroll
    for (int st = 0; st < 2; ++st) {
        #pragma unroll
        for (int j = 0; j < 4; ++j) {
            cp_async16(Asw + st*HAST + 8*j, Ap + st*GBK + 8*j);
            cp_async16(Bsw + st*HBST + 8*j, Bp + st*GBK + 8*j);
        }
        CP_COMMIT();
    }

    int stage = 0;
    for (int i = 0; i < ntiles; ++i) {
        CP_WAIT1();
        __syncthreads();

        const uint32_t abase = asm32 + (uint32_t)stage * (HAST * 2);
        const uint32_t bbase = bsm32 + (uint32_t)stage * (HBST * 2);

        #pragma unroll
        for (int kk = 0; kk < 4; ++kk) {
            unsigned afr[4][4], bfr[4][2];
            #pragma unroll
            for (int mi = 0; mi < 4; ++mi)
                ldm_x4(afr[mi][0], afr[mi][1], afr[mi][2], afr[mi][3],
                       abase + aoff + (uint32_t)mi * (16*HPI*2) + kk*32);
            #pragma unroll
            for (int nj = 0; nj < 2; ++nj) {
                unsigned r0, r1, r2, r3;
                ldm_x4(r0, r1, r2, r3,
                       bbase + boff + (uint32_t)nj * (16*HPI*2) + kk*32);
                bfr[2*nj][0] = r0;   bfr[2*nj][1] = r1;
                bfr[2*nj+1][0] = r2; bfr[2*nj+1][1] = r3;
            }
            #pragma unroll
            for (int mi = 0; mi < 4; ++mi)
                #pragma unroll
                for (int ni = 0; ni < 4; ++ni)
                    mma_h(c[mi][ni], afr[mi], bfr[ni]);
        }

        __syncthreads();

        int nx = i + 2;
        if (nx < ntiles) {
            int ns = nx % HNST;
            #pragma unroll
            for (int j = 0; j < 4; ++j) {
                cp_async16(Asw + ns*HAST + 8*j, Ap + nx*GBK + 8*j);
                cp_async16(Bsw + ns*HBST + 8*j, Bp + nx*GBK + 8*j);
            }
        }
        CP_COMMIT();
        stage = (stage + 1 == HNST) ? 0 : stage + 1;
    }

    // epilogue
    #pragma unroll
    for (int mi = 0; mi < 4; ++mi) {
        #pragma unroll
        for (int ni = 0; ni < 4; ++ni) {
            int row = m0 + warp_m*64 + mi*16 + g;
            int col = n0 + warp_n*32 + ni*8 + 2*t;
            float2 bb = *(const float2*)(bias + col);
            float v00 = c[mi][ni][0] + bb.x, v01 = c[mi][ni][1] + bb.y;
            float v10 = c[mi][ni][2] + bb.x, v11 = c[mi][ni][3] + bb.y;
            if (OUTF32) {
                float* Cf = (float*)Cout;
                float2 o0 = {v00, v01}, o1 = {v10, v11};
                *(float2*)(Cf + (size_t)row * Ndim + col) = o0;
                *(float2*)(Cf + (size_t)(row + 8) * Ndim + col) = o1;
            } else {
                __half* Ch = (__half*)Cout;
                *(unsigned*)(Ch + (size_t)row * Ndim + col) = pack_h2(v00, v01);
                *(unsigned*)(Ch + (size_t)(row + 8) * Ndim + col) = pack_h2(v10, v11);
            }
        }
    }
}

// ---------------------------------------------------------------------------
// fp16 flash attention v2 (unchanged from R14).
// ---------------------------------------------------------------------------
#define QTILE 128
#define KTILE 64
#define HP 72
#define NEG_BIG (-1e30f)
#define KVSTR (KTILE*HP*2)
#define ATTN_SMEM ((QTILE*HP + 2*KTILE*HP + 2*KTILE*HP) * 2)   // 55296 B

__global__ __launch_bounds__(256)
void attn_h2_kernel(const __half* __restrict__ qkv, __half* __restrict__ Y)
{
    extern __shared__ __half smh[];
    __half* Qs  = smh;
    __half* Kst = Qs + QTILE * HP;
    __half* Vst = Kst + 2 * KTILE * HP;

    const int bh = blockIdx.y;
    const int b  = bh >> 4;
    const int h  = bh & 15;
    const int q0 = blockIdx.x * QTILE;

    const int tid  = threadIdx.x;
    const int lane = tid & 31;
    const int wid  = tid >> 5;
    const int g    = lane >> 2;
    const int t    = lane & 3;
    const int wr   = wid * 16;

    const uint32_t qb32 = (uint32_t)__cvta_generic_to_shared(Qs);
    const uint32_t kb32 = (uint32_t)__cvta_generic_to_shared(Kst);
    const uint32_t vb32 = (uint32_t)__cvta_generic_to_shared(Vst);

    const int grp = lane >> 3, l7 = lane & 7;
    const uint32_t qoff = ((uint32_t)(wr + (lane & 15)) * HP + (uint32_t)(lane >> 4) * 8) * 2;
    const uint32_t koff = ((uint32_t)((grp >> 1) * 8 + l7) * HP) * 2 + (uint32_t)(grp & 1) * 16;
    const uint32_t voff = ((uint32_t)((grp & 1) * 8 + l7) * HP) * 2 + (uint32_t)(grp >> 1) * 16;

    const size_t tok_base = (size_t)b * TT * N_QKV;
    const float scale = 0.03125f;

    const int q_hi  = q0 + wr + 15;
    const int ktmax = (q0 + QTILE - 1) / KTILE;

    #pragma unroll
    for (int it = 0; it < 4; ++it) {
        int idx = tid + it * 256;
        int r = idx >> 3, q8 = idx & 7;
        cp_async16(Qs + r * HP + 8*q8,
                   qkv + tok_base + (size_t)(q0 + r) * N_QKV + h*DD + 8*q8);
    }
    #pragma unroll
    for (int it = 0; it < 2; ++it) {
        int idx = tid + it * 256;
        int r = idx >> 3, q8 = idx & 7;
        size_t rowb = tok_base + (size_t)r * N_QKV + h*DD + 8*q8;
        cp_async16(Kst + r * HP + 8*q8, qkv + rowb + CC);
        cp_async16(Vst + r * HP + 8*q8, qkv + rowb + 2*CC);
    }
    CP_COMMIT();
    if (ktmax >= 1) {
        #pragma unroll
        for (int it = 0; it < 2; ++it) {
            int idx = tid + it * 256;
            int r = idx >> 3, q8 = idx & 7;
            size_t rowb = tok_base + (size_t)(KTILE + r) * N_QKV + h*DD + 8*q8;
            cp_async16(Kst + KTILE*HP + r * HP + 8*q8, qkv + rowb + CC);
            cp_async16(Vst + KTILE*HP + r * HP + 8*q8, qkv + rowb + 2*CC);
        }
    }
    CP_COMMIT();
    CP_WAIT1();
    __syncthreads();

    unsigned qa[4][4];
    #pragma unroll
    for (int kk = 0; kk < 4; ++kk)
        ldm_x4(qa[kk][0], qa[kk][1], qa[kk][2], qa[kk][3], qb32 + qoff + kk*32);

    float o[8][4];
    #pragma unroll
    for (int n = 0; n < 8; ++n)
        #pragma unroll
        for (int j = 0; j < 4; ++j) o[n][j] = 0.f;
    float mrow[2] = {NEG_BIG, NEG_BIG};
    float lrow[2] = {0.f, 0.f};

    for (int kt = 0; kt <= ktmax; ++kt) {
        const int k0 = kt * KTILE;
        const uint32_t kbase = kb32 + (uint32_t)(kt & 1) * KVSTR;
        const uint32_t vbase = vb32 + (uint32_t)(kt & 1) * KVSTR;

        if (k0 <= q_hi) {
            float s[8][4];
            #pragma unroll
            for (int n = 0; n < 8; ++n)
                #pragma unroll
                for (int j = 0; j < 4; ++j) s[n][j] = 0.f;

            #pragma unroll
            for (int kk = 0; kk < 4; ++kk) {
                #pragma unroll
                for (int p = 0; p < 4; ++p) {
                    unsigned r0, r1, r2, r3;
                    ldm_x4(r0, r1, r2, r3, kbase + koff + (uint32_t)p * (16*HP*2) + kk*32);
                    unsigned b0[2] = {r0, r1}, b1[2] = {r2, r3};
                    mma_h(s[2*p],     qa[kk], b0);
                    mma_h(s[2*p + 1], qa[kk], b1);
                }
            }

            #pragma unroll
            for (int n = 0; n < 8; ++n)
                #pragma unroll
                for (int j = 0; j < 4; ++j) s[n][j] *= scale;

            if (k0 + KTILE - 1 > q0 + wr) {
                int r0q = q0 + wr + g, r1q = r0q + 8;
                #pragma unroll
                for (int n = 0; n < 8; ++n) {
                    int key = k0 + n*8 + 2*t;
                    if (key     > r0q) s[n][0] = NEG_BIG;
                    if (key + 1 > r0q) s[n][1] = NEG_BIG;
                    if (key     > r1q) s[n][2] = NEG_BIG;
                    if (key + 1 > r1q) s[n][3] = NEG_BIG;
                }
            }

            #pragma unroll
            for (int half = 0; half < 2; ++half) {
                float rm = NEG_BIG;
                #pragma unroll
                for (int n = 0; n < 8; ++n)
                    rm = fmaxf(rm, fmaxf(s[n][2*half], s[n][2*half+1]));
                rm = fmaxf(rm, __shfl_xor_sync(0xffffffffu, rm, 1));
                rm = fmaxf(rm, __shfl_xor_sync(0xffffffffu, rm, 2));
                float mn = fmaxf(mrow[half], rm);
                float alpha = __expf(mrow[half] - mn);
                float ps = 0.f;
                #pragma unroll
                for (int n = 0; n < 8; ++n) {
                    float p0 = __expf(s[n][2*half]   - mn);
                    float p1 = __expf(s[n][2*half+1] - mn);
                    s[n][2*half] = p0; s[n][2*half+1] = p1;
                    ps += p0 + p1;
                }
                ps += __shfl_xor_sync(0xffffffffu, ps, 1);
                ps += __shfl_xor_sync(0xffffffffu, ps, 2);
                lrow[half] = lrow[half] * alpha + ps;
                mrow[half] = mn;
                #pragma unroll
                for (int n = 0; n < 8; ++n) {
                    o[n][2*half]   *= alpha;
                    o[n][2*half+1] *= alpha;
                }
            }

            #pragma unroll
            for (int kk = 0; kk < 4; ++kk) {
                unsigned pa[4];
                pa[0] = pack_h2(s[2*kk][0],     s[2*kk][1]);
                pa[1] = pack_h2(s[2*kk][2],     s[2*kk][3]);
                pa[2] = pack_h2(s[2*kk + 1][0], s[2*kk + 1][1]);
                pa[3] = pack_h2(s[2*kk + 1][2], s[2*kk + 1][3]);
                #pragma unroll
                for (int p = 0; p < 4; ++p) {
                    unsigned r0, r1, r2, r3;
                    ldm_x4_t(r0, r1, r2, r3, vbase + voff + (uint32_t)kk * (16*HP*2) + p*32);
                    unsigned b0[2] = {r0, r1}, b1[2] = {r2, r3};
                    mma_h(o[2*p],     pa, b0);
                    mma_h(o[2*p + 1], pa, b1);
                }
            }
        }

        __syncthreads();

        if (kt + 2 <= ktmax) {
            int k0n = (kt + 2) * KTILE;
            int st = kt & 1;
            #pragma unroll
            for (int it = 0; it < 2; ++it) {
                int idx = tid + it * 256;
                int r = idx >> 3, q8 = idx & 7;
                size_t rowb = tok_base + (size_t)(k0n + r) * N_QKV + h*DD + 8*q8;
                cp_async16(Kst + st*KTILE*HP + r * HP + 8*q8, qkv + rowb + CC);
                cp_async16(Vst + st*KTILE*HP + r * HP + 8*q8, qkv + rowb + 2*CC);
            }
        }
        CP_COMMIT();
        CP_WAIT1();
        __syncthreads();
    }

    #pragma unroll
    for (int half = 0; half < 2; ++half) {
        float inv = 1.0f / lrow[half];
        int row = q0 + wr + g + half * 8;
        __half* yb = Y + (size_t)(b * TT + row) * CC + h*DD + 2*t;
        #pragma unroll
        for (int n = 0; n < 8; ++n)
            *(unsigned*)(yb + n*8) = pack_h2(o[n][2*half] * inv, o[n][2*half+1] * inv);
    }
}

// ---------------------------------------------------------------------------
// Launch
// ---------------------------------------------------------------------------
extern "C" void kernel_launch(void* const* d_in, const int* in_sizes, int n_in,
                              void* d_out, int out_size)
{
    const float* x      = (const float*)d_in[0];
    const float* W_attn = (const float*)d_in[1];
    const float* b_attn = (const float*)d_in[2];
    const float* W_proj = (const float*)d_in[3];
    const float* b_proj = (const float*)d_in[4];
    float* out = (float*)d_out;

    __half *qkv_ptr, *y_ptr, *xh_ptr, *wa_ptr, *wp_ptr;
    cudaGetSymbolAddress((void**)&qkv_ptr, g_qkv);
    cudaGetSymbolAddress((void**)&y_ptr, g_y);
    cudaGetSymbolAddress((void**)&xh_ptr, g_xh);
    cudaGetSymbolAddress((void**)&wa_ptr, g_wa);
    cudaGetSymbolAddress((void**)&wp_ptr, g_wp);

    cudaFuncSetAttribute(attn_h2_kernel, cudaFuncAttributeMaxDynamicSharedMemorySize, ATTN_SMEM);
    cudaFuncSetAttribute(gemm_h<0>, cudaFuncAttributeMaxDynamicSharedMemorySize, GEMMH_SMEM);
    cudaFuncSetAttribute(gemm_h<1>, cudaFuncAttributeMaxDynamicSharedMemorySize, GEMMH_SMEM);

    // 0) pre-pass
    {
        int n4 = M_TOK * CC / 4;
        to_half_kernel<<<(n4 + 255)/256, 256>>>(x, (unsigned*)xh_ptr, n4);
        transpose_h_kernel<<<dim3(N_QKV/32, CC/32), dim3(32, 8)>>>(W_attn, wa_ptr, CC, N_QKV);
        transpose_h_kernel<<<dim3(CC/32, CC/32), dim3(32, 8)>>>(W_proj, wp_ptr, CC, CC);
    }

    // 1) qkv = x @ W_attn + b_attn   (fp16 out)
    gemm_h<0><<<dim3(N_QKV/GBN, M_TOK/GBM), 256, GEMMH_SMEM>>>(
        xh_ptr, wa_ptr, b_attn, qkv_ptr, M_TOK, N_QKV, CC);

    // 2) flash attention v2
    attn_h2_kernel<<<dim3(TT/QTILE, BB*HH), 256, ATTN_SMEM>>>(qkv_ptr, y_ptr);

    // 3) out = y @ W_proj + b_proj   (fp32 out)
    gemm_h<1><<<dim3(CC/GBN, M_TOK/GBM), 256, GEMMH_SMEM>>>(
        y_ptr, wp_ptr, b_proj, out, M_TOK, CC, CC);
}

// round 17
// speedup vs baseline: 1.1751x; 1.1751x over previous
#include <cuda_runtime.h>
#include <cuda_fp16.h>
#include <math.h>
#include <stdint.h>

// Problem constants
#define BB 2
#define TT 2048
#define CC 1024
#define HH 16
#define DD 64
#define M_TOK (BB*TT)     // 4096
#define N_QKV (3*CC)      // 3072

// Scratch (allocation-free rule: __device__ globals)
__device__ __half g_qkv[M_TOK * N_QKV];  // 24 MB
__device__ __half g_y[M_TOK * CC];       //  8 MB
__device__ __half g_xh[M_TOK * CC];      //  8 MB
__device__ __half g_wa[N_QKV * CC];      //  6 MB : W_attn^T [N,K]
__device__ __half g_wp[CC * CC];         //  2 MB : W_proj^T [N,K]

// ---------------------------------------------------------------------------
// helpers
// ---------------------------------------------------------------------------
__device__ __forceinline__ unsigned pack_h2(float a, float b) {
    __half2 h = __floats2half2_rn(a, b);
    return *reinterpret_cast<unsigned*>(&h);
}

__device__ __forceinline__ void mma_h(float c[4], const unsigned a[4], const unsigned b[2]) {
    asm volatile(
        "mma.sync.aligned.m16n8k16.row.col.f32.f16.f16.f32 "
        "{%0,%1,%2,%3}, {%4,%5,%6,%7}, {%8,%9}, {%0,%1,%2,%3};\n"
        : "+f"(c[0]), "+f"(c[1]), "+f"(c[2]), "+f"(c[3])
        : "r"(a[0]), "r"(a[1]), "r"(a[2]), "r"(a[3]), "r"(b[0]), "r"(b[1]));
}

__device__ __forceinline__ void ldm_x4(unsigned& r0, unsigned& r1, unsigned& r2, unsigned& r3,
                                       uint32_t addr) {
    asm volatile("ldmatrix.sync.aligned.m8n8.x4.shared.b16 {%0,%1,%2,%3}, [%4];"
                 : "=r"(r0), "=r"(r1), "=r"(r2), "=r"(r3) : "r"(addr));
}
__device__ __forceinline__ void ldm_x4_t(unsigned& r0, unsigned& r1, unsigned& r2, unsigned& r3,
                                         uint32_t addr) {
    asm volatile("ldmatrix.sync.aligned.m8n8.x4.trans.shared.b16 {%0,%1,%2,%3}, [%4];"
                 : "=r"(r0), "=r"(r1), "=r"(r2), "=r"(r3) : "r"(addr));
}

__device__ __forceinline__ void cp_async16(void* smem, const void* gmem) {
    unsigned saddr = (unsigned)__cvta_generic_to_shared(smem);
    asm volatile("cp.async.cg.shared.global [%0], [%1], 16;\n" :: "r"(saddr), "l"(gmem));
}
#define CP_COMMIT() asm volatile("cp.async.commit_group;\n" ::: "memory")
#define CP_WAIT1()  asm volatile("cp.async.wait_group 1;\n" ::: "memory")
#define CP_WAIT2()  asm volatile("cp.async.wait_group 2;\n" ::: "memory")

// ---------------------------------------------------------------------------
// pre-pass kernels
// ---------------------------------------------------------------------------
__global__ void to_half_kernel(const float* __restrict__ in, unsigned* __restrict__ out, int n4)
{
    int i = blockIdx.x * blockDim.x + threadIdx.x;
    if (i < n4) {
        float4 v = ((const float4*)in)[i];
        uint2 o;
        o.x = pack_h2(v.x, v.y);
        o.y = pack_h2(v.z, v.w);
        ((uint2*)out)[i] = o;
    }
}

__global__ void transpose_h_kernel(const float* __restrict__ in, __half* __restrict__ out,
                                   int K, int N)
{
    __shared__ float tile[32][33];
    int k0 = blockIdx.y * 32, n0 = blockIdx.x * 32;
    int tx = threadIdx.x, ty = threadIdx.y;
    #pragma unroll
    for (int j = 0; j < 4; ++j)
        tile[ty + 8*j][tx] = in[(size_t)(k0 + ty + 8*j) * N + n0 + tx];
    __syncthreads();
    #pragma unroll
    for (int j = 0; j < 4; ++j)
        out[(size_t)(n0 + ty + 8*j) * K + k0 + tx] = __float2half_rn(tile[tx][ty + 8*j]);
}

// ---------------------------------------------------------------------------
// fp16 GEMM (R14 config, single-barrier mainloop):
// BM=128, BN=128, BK=32, 256 threads, 2 CTAs/SM, ldmatrix frags, 3-stage.
// Warp tile 64x32 (8 warps, 2 along M x 4 along N).
// C[M,N] = A[M,K] @ Bt[N,K]^T + bias[N].
// ---------------------------------------------------------------------------
#define GBM 128
#define GBN 128
#define GBK 32
#define HNST 3
#define HPI 40                      // pitch (halves); 80B rows -> ldmatrix conflict-free
#define HAST (GBM * HPI)            // 5120 halves / stage
#define HBST (GBN * HPI)
#define GEMMH_SMEM ((HNST*(HAST + HBST)) * 2)   // 61440 B

template<int OUTF32>
__global__ __launch_bounds__(256, 2)
void gemm_h(const __half* __restrict__ A, const __half* __restrict__ Bt,
            const float* __restrict__ bias, void* __restrict__ Cout,
            int Mdim, int Ndim, int Kdim)
{
    extern __shared__ __half hsm[];
    __half* As = hsm;                       // [HNST][128][HPI]
    __half* Bs = hsm + HNST * HAST;         // [HNST][128][HPI]

    const int tid  = threadIdx.x;
    const int lane = tid & 31;
    const int wid  = tid >> 5;
    const int g    = lane >> 2;
    const int t    = lane & 3;
    const int warp_m = wid & 1;             // 2 warps along M (64 rows)
    const int warp_n = wid >> 1;            // 4 warps along N (32 cols)
    const int m0 = blockIdx.y * GBM;
    const int n0 = blockIdx.x * GBN;

    // cp.async mapping: rows r, r+64; unit au (4 x 16B per 64-half row)
    const int arow = tid >> 2, au = tid & 3;

    const __half* Ap = A  + (size_t)(m0 + arow) * Kdim + 8 * au;
    const __half* Bp = Bt + (size_t)(n0 + arow) * Kdim + 8 * au;

    __half* Asw = As + arow * HPI + 8 * au;
    __half* Bsw = Bs + arow * HPI + 8 * au;

    // ldmatrix per-lane offsets (byte)
    const int grp = lane >> 3, l7 = lane & 7;
    const uint32_t asm32 = (uint32_t)__cvta_generic_to_shared(As);
    const uint32_t bsm32 = (uint32_t)__cvta_generic_to_shared(Bs);
    const uint32_t aoff = ((uint32_t)(warp_m*64 + (lane & 15)) * HPI + (uint32_t)(lane >> 4) * 8) * 2;
    const uint32_t boff = ((uint32_t)(warp_n*32 + (grp >> 1)*8 + l7) * HPI) * 2 + (uint32_t)(grp & 1) * 16;

    float c[4][4][4];
    #pragma unroll
    for (int mi = 0; mi < 4; ++mi)
        #pragma unroll
        for (int ni = 0; ni < 4; ++ni)
            #pragma unroll
            for (int j = 0; j < 4; ++j) c[mi][ni][j] = 0.f;

    const int ntiles = Kdim / GBK;

    // prologue: fill stages 0,1
    #pragma unroll
    for (int st = 0; st < 2; ++st) {
        cp_async16(Asw + st*HAST,           Ap + st*GBK);
        cp_async16(Asw + st*HAST + 64*HPI,  Ap + (size_t)64*Kdim + st*GBK);
        cp_async16(Bsw + st*HBST,           Bp + st*GBK);
        cp_async16(Bsw + st*HBST + 64*HPI,  Bp + (size_t)64*Kdim + st*GBK);
        CP_COMMIT();
    }

    int stage = 0;
    for (int i = 0; i < ntiles; ++i) {
        CP_WAIT1();          // tile i resident
        __syncthreads();     // all warps done with stage (i+2)%3's previous contents

        // refill stage (i+2)%3 immediately — overlaps with this iteration's mma
        int nx = i + 2;
        if (nx < ntiles) {
            int ns = nx % HNST;
            cp_async16(Asw + ns*HAST,          Ap + nx*GBK);
            cp_async16(Asw + ns*HAST + 64*HPI, Ap + (size_t)64*Kdim + nx*GBK);
            cp_async16(Bsw + ns*HBST,          Bp + nx*GBK);
            cp_async16(Bsw + ns*HBST + 64*HPI, Bp + (size_t)64*Kdim + nx*GBK);
        }
        CP_COMMIT();

        const uint32_t abase = asm32 + (uint32_t)stage * (HAST * 2);
        const uint32_t bbase = bsm32 + (uint32_t)stage * (HBST * 2);

        #pragma unroll
        for (int kk = 0; kk < 2; ++kk) {
            unsigned afr[4][4], bfr[4][2];
            #pragma unroll
            for (int mi = 0; mi < 4; ++mi)
                ldm_x4(afr[mi][0], afr[mi][1], afr[mi][2], afr[mi][3],
                       abase + aoff + (uint32_t)mi * (16*HPI*2) + kk*32);
            #pragma unroll
            for (int nj = 0; nj < 2; ++nj) {
                unsigned r0, r1, r2, r3;
                ldm_x4(r0, r1, r2, r3,
                       bbase + boff + (uint32_t)nj * (16*HPI*2) + kk*32);
                bfr[2*nj][0] = r0;   bfr[2*nj][1] = r1;
                bfr[2*nj+1][0] = r2; bfr[2*nj+1][1] = r3;
            }
            #pragma unroll
            for (int mi = 0; mi < 4; ++mi)
                #pragma unroll
                for (int ni = 0; ni < 4; ++ni)
                    mma_h(c[mi][ni], afr[mi], bfr[ni]);
        }

        stage = (stage + 1 == HNST) ? 0 : stage + 1;
    }

    // epilogue
    #pragma unroll
    for (int mi = 0; mi < 4; ++mi) {
        #pragma unroll
        for (int ni = 0; ni < 4; ++ni) {
            int row = m0 + warp_m*64 + mi*16 + g;
            int col = n0 + warp_n*32 + ni*8 + 2*t;
            float2 bb = *(const float2*)(bias + col);
            float v00 = c[mi][ni][0] + bb.x, v01 = c[mi][ni][1] + bb.y;
            float v10 = c[mi][ni][2] + bb.x, v11 = c[mi][ni][3] + bb.y;
            if (OUTF32) {
                float* Cf = (float*)Cout;
                float2 o0 = {v00, v01}, o1 = {v10, v11};
                *(float2*)(Cf + (size_t)row * Ndim + col) = o0;
                *(float2*)(Cf + (size_t)(row + 8) * Ndim + col) = o1;
            } else {
                __half* Ch = (__half*)Cout;
                *(unsigned*)(Ch + (size_t)row * Ndim + col) = pack_h2(v00, v01);
                *(unsigned*)(Ch + (size_t)(row + 8) * Ndim + col) = pack_h2(v10, v11);
            }
        }
    }
}

// ---------------------------------------------------------------------------
// fp16 flash attention v2 (unchanged from R14 / the 272.9 µs best).
// ---------------------------------------------------------------------------
#define QTILE 128
#define KTILE 64
#define HP 72
#define NEG_BIG (-1e30f)
#define KVSTR (KTILE*HP*2)
#define ATTN_SMEM ((QTILE*HP + 2*KTILE*HP + 2*KTILE*HP) * 2)   // 55296 B

__global__ __launch_bounds__(256)
void attn_h2_kernel(const __half* __restrict__ qkv, __half* __restrict__ Y)
{
    extern __shared__ __half smh[];
    __half* Qs  = smh;
    __half* Kst = Qs + QTILE * HP;
    __half* Vst = Kst + 2 * KTILE * HP;

    const int bh = blockIdx.y;
    const int b  = bh >> 4;
    const int h  = bh & 15;
    const int q0 = blockIdx.x * QTILE;

    const int tid  = threadIdx.x;
    const int lane = tid & 31;
    const int wid  = tid >> 5;
    const int g    = lane >> 2;
    const int t    = lane & 3;
    const int wr   = wid * 16;

    const uint32_t qb32 = (uint32_t)__cvta_generic_to_shared(Qs);
    const uint32_t kb32 = (uint32_t)__cvta_generic_to_shared(Kst);
    const uint32_t vb32 = (uint32_t)__cvta_generic_to_shared(Vst);

    const int grp = lane >> 3, l7 = lane & 7;
    const uint32_t qoff = ((uint32_t)(wr + (lane & 15)) * HP + (uint32_t)(lane >> 4) * 8) * 2;
    const uint32_t koff = ((uint32_t)((grp >> 1) * 8 + l7) * HP) * 2 + (uint32_t)(grp & 1) * 16;
    const uint32_t voff = ((uint32_t)((grp & 1) * 8 + l7) * HP) * 2 + (uint32_t)(grp >> 1) * 16;

    const size_t tok_base = (size_t)b * TT * N_QKV;
    const float scale = 0.03125f;

    const int q_hi  = q0 + wr + 15;
    const int ktmax = (q0 + QTILE - 1) / KTILE;

    #pragma unroll
    for (int it = 0; it < 4; ++it) {
        int idx = tid + it * 256;
        int r = idx >> 3, q8 = idx & 7;
        cp_async16(Qs + r * HP + 8*q8,
                   qkv + tok_base + (size_t)(q0 + r) * N_QKV + h*DD + 8*q8);
    }
    #pragma unroll
    for (int it = 0; it < 2; ++it) {
        int idx = tid + it * 256;
        int r = idx >> 3, q8 = idx & 7;
        size_t rowb = tok_base + (size_t)r * N_QKV + h*DD + 8*q8;
        cp_async16(Kst + r * HP + 8*q8, qkv + rowb + CC);
        cp_async16(Vst + r * HP + 8*q8, qkv + rowb + 2*CC);
    }
    CP_COMMIT();
    if (ktmax >= 1) {
        #pragma unroll
        for (int it = 0; it < 2; ++it) {
            int idx = tid + it * 256;
            int r = idx >> 3, q8 = idx & 7;
            size_t rowb = tok_base + (size_t)(KTILE + r) * N_QKV + h*DD + 8*q8;
            cp_async16(Kst + KTILE*HP + r * HP + 8*q8, qkv + rowb + CC);
            cp_async16(Vst + KTILE*HP + r * HP + 8*q8, qkv + rowb + 2*CC);
        }
    }
    CP_COMMIT();
    CP_WAIT1();
    __syncthreads();

    unsigned qa[4][4];
    #pragma unroll
    for (int kk = 0; kk < 4; ++kk)
        ldm_x4(qa[kk][0], qa[kk][1], qa[kk][2], qa[kk][3], qb32 + qoff + kk*32);

    float o[8][4];
    #pragma unroll
    for (int n = 0; n < 8; ++n)
        #pragma unroll
        for (int j = 0; j < 4; ++j) o[n][j] = 0.f;
    float mrow[2] = {NEG_BIG, NEG_BIG};
    float lrow[2] = {0.f, 0.f};

    for (int kt = 0; kt <= ktmax; ++kt) {
        const int k0 = kt * KTILE;
        const uint32_t kbase = kb32 + (uint32_t)(kt & 1) * KVSTR;
        const uint32_t vbase = vb32 + (uint32_t)(kt & 1) * KVSTR;

        if (k0 <= q_hi) {
            float s[8][4];
            #pragma unroll
            for (int n = 0; n < 8; ++n)
                #pragma unroll
                for (int j = 0; j < 4; ++j) s[n][j] = 0.f;

            #pragma unroll
            for (int kk = 0; kk < 4; ++kk) {
                #pragma unroll
                for (int p = 0; p < 4; ++p) {
                    unsigned r0, r1, r2, r3;
                    ldm_x4(r0, r1, r2, r3, kbase + koff + (uint32_t)p * (16*HP*2) + kk*32);
                    unsigned b0[2] = {r0, r1}, b1[2] = {r2, r3};
                    mma_h(s[2*p],     qa[kk], b0);
                    mma_h(s[2*p + 1], qa[kk], b1);
                }
            }

            #pragma unroll
            for (int n = 0; n < 8; ++n)
                #pragma unroll
                for (int j = 0; j < 4; ++j) s[n][j] *= scale;

            if (k0 + KTILE - 1 > q0 + wr) {
                int r0q = q0 + wr + g, r1q = r0q + 8;
                #pragma unroll
                for (int n = 0; n < 8; ++n) {
                    int key = k0 + n*8 + 2*t;
                    if (key     > r0q) s[n][0] = NEG_BIG;
                    if (key + 1 > r0q) s[n][1] = NEG_BIG;
                    if (key     > r1q) s[n][2] = NEG_BIG;
                    if (key + 1 > r1q) s[n][3] = NEG_BIG;
                }
            }

            #pragma unroll
            for (int half = 0; half < 2; ++half) {
                float rm = NEG_BIG;
                #pragma unroll
                for (int n = 0; n < 8; ++n)
                    rm = fmaxf(rm, fmaxf(s[n][2*half], s[n][2*half+1]));
                rm = fmaxf(rm, __shfl_xor_sync(0xffffffffu, rm, 1));
                rm = fmaxf(rm, __shfl_xor_sync(0xffffffffu, rm, 2));
                float mn = fmaxf(mrow[half], rm);
                float alpha = __expf(mrow[half] - mn);
                float ps = 0.f;
                #pragma unroll
                for (int n = 0; n < 8; ++n) {
                    float p0 = __expf(s[n][2*half]   - mn);
                    float p1 = __expf(s[n][2*half+1] - mn);
                    s[n][2*half] = p0; s[n][2*half+1] = p1;
                    ps += p0 + p1;
                }
                ps += __shfl_xor_sync(0xffffffffu, ps, 1);
                ps += __shfl_xor_sync(0xffffffffu, ps, 2);
                lrow[half] = lrow[half] * alpha + ps;
                mrow[half] = mn;
                #pragma unroll
                for (int n = 0; n < 8; ++n) {
                    o[n][2*half]   *= alpha;
                    o[n][2*half+1] *= alpha;
                }
            }

            #pragma unroll
            for (int kk = 0; kk < 4; ++kk) {
                unsigned pa[4];
                pa[0] = pack_h2(s[2*kk][0],     s[2*kk][1]);
                pa[1] = pack_h2(s[2*kk][2],     s[2*kk][3]);
                pa[2] = pack_h2(s[2*kk + 1][0], s[2*kk + 1][1]);
                pa[3] = pack_h2(s[2*kk + 1][2], s[2*kk + 1][3]);
                #pragma unroll
                for (int p = 0; p < 4; ++p) {
                    unsigned r0, r1, r2, r3;
                    ldm_x4_t(r0, r1, r2, r3, vbase + voff + (uint32_t)kk * (16*HP*2) + p*32);
                    unsigned b0[2] = {r0, r1}, b1[2] = {r2, r3};
                    mma_h(o[2*p],     pa, b0);
                    mma_h(o[2*p + 1], pa, b1);
                }
            }
        }

        __syncthreads();

        if (kt + 2 <= ktmax) {
            int k0n = (kt + 2) * KTILE;
            int st = kt & 1;
            #pragma unroll
            for (int it = 0; it < 2; ++it) {
                int idx = tid + it * 256;
                int r = idx >> 3, q8 = idx & 7;
                size_t rowb = tok_base + (size_t)(k0n + r) * N_QKV + h*DD + 8*q8;
                cp_async16(Kst + st*KTILE*HP + r * HP + 8*q8, qkv + rowb + CC);
                cp_async16(Vst + st*KTILE*HP + r * HP + 8*q8, qkv + rowb + 2*CC);
            }
        }
        CP_COMMIT();
        CP_WAIT1();
        __syncthreads();
    }

    #pragma unroll
    for (int half = 0; half < 2; ++half) {
        float inv = 1.0f / lrow[half];
        int row = q0 + wr + g + half * 8;
        __half* yb = Y + (size_t)(b * TT + row) * CC + h*DD + 2*t;
        #pragma unroll
        for (int n = 0; n < 8; ++n)
            *(unsigned*)(yb + n*8) = pack_h2(o[n][2*half] * inv, o[n][2*half+1] * inv);
    }
}

// ---------------------------------------------------------------------------
// Launch
// ---------------------------------------------------------------------------
extern "C" void kernel_launch(void* const* d_in, const int* in_sizes, int n_in,
                              void* d_out, int out_size)
{
    const float* x      = (const float*)d_in[0];
    const float* W_attn = (const float*)d_in[1];
    const float* b_attn = (const float*)d_in[2];
    const float* W_proj = (const float*)d_in[3];
    const float* b_proj = (const float*)d_in[4];
    float* out = (float*)d_out;

    __half *qkv_ptr, *y_ptr, *xh_ptr, *wa_ptr, *wp_ptr;
    cudaGetSymbolAddress((void**)&qkv_ptr, g_qkv);
    cudaGetSymbolAddress((void**)&y_ptr, g_y);
    cudaGetSymbolAddress((void**)&xh_ptr, g_xh);
    cudaGetSymbolAddress((void**)&wa_ptr, g_wa);
    cudaGetSymbolAddress((void**)&wp_ptr, g_wp);

    cudaFuncSetAttribute(attn_h2_kernel, cudaFuncAttributeMaxDynamicSharedMemorySize, ATTN_SMEM);
    cudaFuncSetAttribute(gemm_h<0>, cudaFuncAttributeMaxDynamicSharedMemorySize, GEMMH_SMEM);
    cudaFuncSetAttribute(gemm_h<1>, cudaFuncAttributeMaxDynamicSharedMemorySize, GEMMH_SMEM);

    // 0) pre-pass
    {
        int n4 = M_TOK * CC / 4;
        to_half_kernel<<<(n4 + 255)/256, 256>>>(x, (unsigned*)xh_ptr, n4);
        transpose_h_kernel<<<dim3(N_QKV/32, CC/32), dim3(32, 8)>>>(W_attn, wa_ptr, CC, N_QKV);
        transpose_h_kernel<<<dim3(CC/32, CC/32), dim3(32, 8)>>>(W_proj, wp_ptr, CC, CC);
    }

    // 1) qkv = x @ W_attn + b_attn   (fp16 out)
    gemm_h<0><<<dim3(N_QKV/GBN, M_TOK/GBM), 256, GEMMH_SMEM>>>(
        xh_ptr, wa_ptr, b_attn, qkv_ptr, M_TOK, N_QKV, CC);

    // 2) flash attention v2
    attn_h2_kernel<<<dim3(TT/QTILE, BB*HH), 256, ATTN_SMEM>>>(qkv_ptr, y_ptr);

    // 3) out = y @ W_proj + b_proj   (fp32 out)
    gemm_h<1><<<dim3(CC/GBN, M_TOK/GBM), 256, GEMMH_SMEM>>>(
        y_ptr, wp_ptr, b_proj, out, M_TOK, CC, CC);
}